// round 1
// baseline (speedup 1.0000x reference)
#include <cuda_runtime.h>
#include <cstdint>

// ---------------------------------------------------------------------------
// FNO fused kernel, sm_103a.
//   h0 = relu(mu @ W1 + b1)
//   h  = relu(h @ B_l + xterm_l)   l=0..3   (circulant form of rfft*fw->irfft)
//   out = h @ W2 + b2
// B_l built on device from fw/lw; weights pre-rounded to tf32 (rna).
// Main kernel: 128 rows/CTA, 512 threads, mma.sync m16n8k8 tf32.
// ---------------------------------------------------------------------------

#define NMODES 256
#define NLAYERS 4
#define MROWS 128
#define NTHREADS 512
#define HS_STRIDE 260   // 128x260 fp32 h tile (pad 4 -> conflict-free A loads)
#define WS_STRIDE 264   // 64x264 fp32 weight chunk (pad 8 -> conflict-free B loads)

__device__ float g_dev[NLAYERS * NMODES];             // irfft(fw_l), fp32
__device__ float Bmat_dev[NLAYERS * NMODES * NMODES]; // tf32-rounded circulant+diag
__device__ float w1r_dev[64 * NMODES];                // tf32-rounded W1

__device__ __forceinline__ uint32_t f2tf(float f) {
    uint32_t u;
    asm("cvt.rna.tf32.f32 %0, %1;" : "=r"(u) : "f"(f));
    return u;
}
__device__ __forceinline__ float tf32r(float f) {
    return __uint_as_float(f2tf(f));
}

// ---- prelude: g_l[n] = irfft(fw_l)[n] ----
__global__ void build_g(const float* __restrict__ fw) {
    int l = blockIdx.x;
    int n = threadIdx.x;
    const float* f = fw + l * 129;
    float acc = f[0] + ((n & 1) ? -f[128] : f[128]);
    float nn = (float)n;
#pragma unroll 4
    for (int k = 1; k < 128; ++k)
        acc += 2.0f * f[k] * cospif((float)k * nn * (1.0f / 128.0f));
    g_dev[l * NMODES + n] = acc * (1.0f / 256.0f);
}

// ---- prelude: B_l[k][n] (tf32-rounded) ----
__global__ void build_B(const float* __restrict__ lw) {
    int l = blockIdx.x >> 8;
    int k = blockIdx.x & 255;
    int n = threadIdx.x;
    float v = (k <= 252) ? g_dev[l * NMODES + ((n - k - 3) & 255)] : 0.0f;
    if (k == n) v += lw[l * NMODES + n];
    Bmat_dev[((size_t)(l * NMODES + k)) * NMODES + n] = tf32r(v);
}

// ---- prelude: round W1 to tf32 ----
__global__ void round_w1(const float* __restrict__ W1) {
    int i = blockIdx.x * 256 + threadIdx.x;
    w1r_dev[i] = tf32r(W1[i]);
}

// ---- mma.sync m16n8k8 tf32 ----
__device__ __forceinline__ void mma8(float* c, const uint32_t a[4], uint32_t b0, uint32_t b1) {
    asm volatile(
        "mma.sync.aligned.m16n8k8.row.col.f32.tf32.tf32.f32 "
        "{%0,%1,%2,%3}, {%4,%5,%6,%7}, {%8,%9}, {%0,%1,%2,%3};\n"
        : "+f"(c[0]), "+f"(c[1]), "+f"(c[2]), "+f"(c[3])
        : "r"(a[0]), "r"(a[1]), "r"(a[2]), "r"(a[3]), "r"(b0), "r"(b1));
}

// per-warp 32x64 output tile; A from h_s (fp32, cvt->tf32 at load), B from w_s
__device__ __forceinline__ void gemm_chunk(float acc[2][8][4],
                                           const float* __restrict__ h_s,
                                           const float* __restrict__ w_s,
                                           int kbase, int wm, int wn, int lg, int tig) {
#pragma unroll
    for (int ks = 0; ks < 8; ++ks) {
        const int kk = ks * 8;
        uint32_t a[2][4];
#pragma unroll
        for (int mt = 0; mt < 2; ++mt) {
            const float* ap = h_s + (wm * 32 + mt * 16 + lg) * HS_STRIDE + kbase + kk;
            a[mt][0] = f2tf(ap[tig]);
            a[mt][1] = f2tf(ap[8 * HS_STRIDE + tig]);
            a[mt][2] = f2tf(ap[tig + 4]);
            a[mt][3] = f2tf(ap[8 * HS_STRIDE + tig + 4]);
        }
#pragma unroll
        for (int nt = 0; nt < 8; ++nt) {
            const float* bp = w_s + (kk + tig) * WS_STRIDE + wn * 64 + nt * 8 + lg;
            uint32_t b0 = __float_as_uint(bp[0]);
            uint32_t b1 = __float_as_uint(bp[4 * WS_STRIDE]);
            mma8(acc[0][nt], a[0], b0, b1);
            mma8(acc[1][nt], a[1], b0, b1);
        }
    }
}

__global__ __launch_bounds__(NTHREADS, 1)
void fno_main(const float* __restrict__ mu, const float* __restrict__ xin,
              const float* __restrict__ b1, const float* __restrict__ W2,
              const float* __restrict__ b2v, float* __restrict__ out) {
    extern __shared__ float sm[];
    float* h_s  = sm;                        // [128][260]
    float* w_s  = h_s + MROWS * HS_STRIDE;   // [64][264]
    float* g_s  = w_s + 64 * WS_STRIDE;      // [256]
    float* x_s  = g_s + NMODES;              // [128][4]
    float* w2_s = x_s + MROWS * 4;           // [256]

    const int tid  = threadIdx.x;
    const int lane = tid & 31;
    const int warp = tid >> 5;
    const int lg   = lane >> 2;  // 0..7
    const int tig  = lane & 3;   // 0..3
    const int wm   = warp >> 2;  // 0..3  (rows)
    const int wn   = warp & 3;   // 0..3  (cols)
    const size_t row0 = (size_t)blockIdx.x * MROWS;

    // x tile, W2
    for (int i = tid; i < MROWS * 3; i += NTHREADS) {
        int r = i / 3, c = i - r * 3;
        x_s[r * 4 + c] = xin[(row0 + r) * 3 + c];
    }
    if (tid < NMODES) w2_s[tid] = W2[tid];

    // mu tile -> h_s cols [0,64)
    for (int i = tid; i < MROWS * 16; i += NTHREADS) {
        int r = i >> 4, c4 = i & 15;
        float4 v = reinterpret_cast<const float4*>(mu + (row0 + r) * 64)[c4];
        float* d = h_s + r * HS_STRIDE + c4 * 4;
        d[0] = v.x; d[1] = v.y; d[2] = v.z; d[3] = v.w;
    }
    // W1 (pre-rounded) -> w_s
    for (int i = tid; i < 64 * 64; i += NTHREADS) {
        int r = i >> 6, c4 = i & 63;
        float4 v = reinterpret_cast<const float4*>(w1r_dev + r * NMODES)[c4];
        float* d = w_s + r * WS_STRIDE + c4 * 4;
        d[0] = v.x; d[1] = v.y; d[2] = v.z; d[3] = v.w;
    }
    __syncthreads();

    float acc[2][8][4];
#pragma unroll
    for (int mt = 0; mt < 2; ++mt)
#pragma unroll
        for (int nt = 0; nt < 8; ++nt)
#pragma unroll
            for (int j = 0; j < 4; ++j) acc[mt][nt][j] = 0.0f;

    // encoder GEMM (K=64)
    gemm_chunk(acc, h_s, w_s, 0, wm, wn, lg, tig);
    __syncthreads();

    // encoder epilogue: +b1, relu -> h_s
#pragma unroll
    for (int mt = 0; mt < 2; ++mt)
#pragma unroll
        for (int half = 0; half < 2; ++half) {
            int r = wm * 32 + mt * 16 + lg + half * 8;
#pragma unroll
            for (int nt = 0; nt < 8; ++nt)
#pragma unroll
                for (int q = 0; q < 2; ++q) {
                    int n = wn * 64 + nt * 8 + 2 * tig + q;
                    float v = acc[mt][nt][half * 2 + q] + b1[n];
                    h_s[r * HS_STRIDE + n] = fmaxf(v, 0.0f);
                }
        }
    __syncthreads();

    // Fourier layers
    for (int l = 0; l < NLAYERS; ++l) {
        if (tid < NMODES) g_s[tid] = g_dev[l * NMODES + tid];
#pragma unroll
        for (int mt = 0; mt < 2; ++mt)
#pragma unroll
            for (int nt = 0; nt < 8; ++nt)
#pragma unroll
                for (int j = 0; j < 4; ++j) acc[mt][nt][j] = 0.0f;

        const float* Bl = Bmat_dev + (size_t)l * NMODES * NMODES;
#pragma unroll 1
        for (int k0 = 0; k0 < NMODES; k0 += 64) {
            __syncthreads();  // previous chunk's mma / h_s writes done
            for (int i = tid; i < 64 * 64; i += NTHREADS) {
                int r = i >> 6, c4 = i & 63;
                float4 v = reinterpret_cast<const float4*>(Bl + (size_t)(k0 + r) * NMODES)[c4];
                float* d = w_s + r * WS_STRIDE + c4 * 4;
                d[0] = v.x; d[1] = v.y; d[2] = v.z; d[3] = v.w;
            }
            __syncthreads();
            gemm_chunk(acc, h_s, w_s, k0, wm, wn, lg, tig);
        }
        __syncthreads();  // all reads of h_s done before overwrite

        // epilogue: + x-term, relu -> h_s
#pragma unroll
        for (int mt = 0; mt < 2; ++mt)
#pragma unroll
            for (int half = 0; half < 2; ++half) {
                int r = wm * 32 + mt * 16 + lg + half * 8;
                float x0 = x_s[r * 4 + 0];
                float x1 = x_s[r * 4 + 1];
                float x2 = x_s[r * 4 + 2];
#pragma unroll
                for (int nt = 0; nt < 8; ++nt)
#pragma unroll
                    for (int q = 0; q < 2; ++q) {
                        int n = wn * 64 + nt * 8 + 2 * tig + q;
                        float v = acc[mt][nt][half * 2 + q];
                        v += x0 * g_s[n] + x1 * g_s[(n + 255) & 255] + x2 * g_s[(n + 254) & 255];
                        h_s[r * HS_STRIDE + n] = fmaxf(v, 0.0f);
                    }
            }
        __syncthreads();
    }

    // decoder: out[r] = h[r,:] . W2 + b2    (512 threads -> 128 rows x 4 parts)
    {
        int r = tid >> 2, part = tid & 3;
        const float* hp = h_s + r * HS_STRIDE + part * 64;
        const float* wp = w2_s + part * 64;
        float s = 0.0f;
#pragma unroll 16
        for (int i = 0; i < 64; ++i) s += hp[i] * wp[i];
        s += __shfl_xor_sync(0xffffffffu, s, 1);
        s += __shfl_xor_sync(0xffffffffu, s, 2);
        if (part == 0) out[row0 + r] = s + b2v[0];
    }
}

// ---------------------------------------------------------------------------
extern "C" void kernel_launch(void* const* d_in, const int* in_sizes, int n_in,
                              void* d_out, int out_size) {
    const float* mu = (const float*)d_in[0];
    const float* x  = (const float*)d_in[1];
    const float* W1 = (const float*)d_in[2];
    const float* b1 = (const float*)d_in[3];
    const float* fw = (const float*)d_in[4];
    const float* lw = (const float*)d_in[5];
    const float* W2 = (const float*)d_in[6];
    const float* b2 = (const float*)d_in[7];
    float* out = (float*)d_out;

    const int B = in_sizes[0] / 64;  // 262144
    const int nblocks = B / MROWS;

    const size_t smem_bytes =
        (size_t)(MROWS * HS_STRIDE + 64 * WS_STRIDE + NMODES + MROWS * 4 + NMODES) * sizeof(float);

    cudaFuncSetAttribute(fno_main, cudaFuncAttributeMaxDynamicSharedMemorySize,
                         (int)smem_bytes);

    build_g<<<NLAYERS, NMODES>>>(fw);
    build_B<<<NLAYERS * NMODES, NMODES>>>(lw);
    round_w1<<<64, 256>>>(W1);
    fno_main<<<nblocks, NTHREADS, smem_bytes>>>(mu, x, b1, W2, b2, out);
}

// round 3
// speedup vs baseline: 1.7519x; 1.7519x over previous
#include <cuda_runtime.h>
#include <cuda_fp16.h>
#include <cstdint>

// ---------------------------------------------------------------------------
// FNO on sm_103a, fp16 HMMA (m16n8k16) + cp.async double-buffered weights.
//   h0 = relu(mu @ W1 + b1)
//   h  = relu(h @ B_l + x-term_l)   l=0..3  (circulant form of rfft*fw->irfft)
//   out = h @ W2 + b2
// h tile: 128x256 fp16 in SMEM (words, stride-padded). Weights pre-built as
// fp16 [n][k] (n-major) in global; streamed in 64-K chunks of 32KB via
// cp.async, double buffered. Final layer h stored fp32 for the decoder.
// ---------------------------------------------------------------------------

#define NMODES 256
#define NLAYERS 4
#define MROWS 128
#define NTHREADS 512
#define HW 132                      // h row stride in 32-bit words (128 + pad 4)
#define WW 36                       // weight row stride in words (32 + pad 4)
#define H_BYTES (MROWS * HW * 4)    // 67584
#define WBUF0_OFF H_BYTES
#define WBUF_BYTES (NMODES * WW * 4)        // 36864
#define WBUF1_OFF (WBUF0_OFF + WBUF_BYTES)  // 104448
#define G_OFF  (WBUF1_OFF + WBUF_BYTES)     // 141312
#define X_OFF  (G_OFF + 5 * NMODES * 4)     // 146432
#define W2_OFF (X_OFF + MROWS * 4 * 4)      // 148480
#define SMEM_TOTAL (W2_OFF + NMODES * 4)    // 149504
#define FH_STRIDE 260               // final fp32 h row stride (floats), at smem+0

__device__ float  g_dev[NLAYERS * NMODES];
__device__ __align__(16) __half Bt_h[NLAYERS * NMODES * NMODES]; // [l][n][k]
__device__ __align__(16) __half w1t_h[NMODES * 64];              // [n][k]

__device__ __forceinline__ uint32_t smem_u32(const void* p) {
    uint32_t a;
    asm("{ .reg .u64 t; cvta.to.shared.u64 t, %1; cvt.u32.u64 %0, t; }" : "=r"(a) : "l"(p));
    return a;
}

#define CP_ASYNC16(dst, src) \
    asm volatile("cp.async.cg.shared.global [%0], [%1], 16;" :: "r"(dst), "l"(src) : "memory")
#define CP_COMMIT() asm volatile("cp.async.commit_group;" ::: "memory")
#define CP_WAIT(n)  asm volatile("cp.async.wait_group %0;" :: "n"(n) : "memory")

__device__ __forceinline__ void mma16(float* c, const uint32_t a[4], uint32_t b0, uint32_t b1) {
    asm volatile(
        "mma.sync.aligned.m16n8k16.row.col.f32.f16.f16.f32 "
        "{%0,%1,%2,%3}, {%4,%5,%6,%7}, {%8,%9}, {%0,%1,%2,%3};\n"
        : "+f"(c[0]), "+f"(c[1]), "+f"(c[2]), "+f"(c[3])
        : "r"(a[0]), "r"(a[1]), "r"(a[2]), "r"(a[3]), "r"(b0), "r"(b1));
}

// ---------------- preludes ----------------
__global__ void build_g(const float* __restrict__ fw) {
    int l = blockIdx.x, n = threadIdx.x;
    const float* f = fw + l * 129;
    float acc = f[0] + ((n & 1) ? -f[128] : f[128]);
    float nn = (float)n;
#pragma unroll 4
    for (int k = 1; k < 128; ++k)
        acc += 2.0f * f[k] * cospif((float)k * nn * (1.0f / 128.0f));
    g_dev[l * NMODES + n] = acc * (1.0f / 256.0f);
}

__global__ void build_Bth(const float* __restrict__ lw) {
    int l = blockIdx.x >> 8, n = blockIdx.x & 255, k = threadIdx.x;
    float v = (k <= 252) ? g_dev[l * NMODES + ((n - k - 3) & 255)] : 0.0f;
    if (k == n) v += lw[l * NMODES + k];
    Bt_h[((size_t)(l * NMODES + n)) * NMODES + k] = __float2half_rn(v);
}

__global__ void build_w1th(const float* __restrict__ W1) {
    int n = blockIdx.x, k = threadIdx.x;
    w1t_h[n * 64 + k] = __float2half_rn(W1[k * NMODES + n]);
}

// ---------------- weight-chunk prefetch (cp.async) ----------------
// chunk id 0: encoder (w1t_h, 256 rows x 64 halves)
// chunk id 1..16: layer (id-1)>>2, k0 = ((id-1)&3)*64 of Bt_h
__device__ __forceinline__ void prefetch_chunk(int id, uint32_t wsmem, int tid) {
    const __half* gb;
    int rowstride;
    if (id == 0) { gb = w1t_h; rowstride = 64; }
    else {
        int t = id - 1;
        gb = Bt_h + (((size_t)((t >> 2) * NMODES)) << 8) + (t & 3) * 64;
        rowstride = NMODES;
    }
#pragma unroll
    for (int i = 0; i < 4; ++i) {
        int idx = tid + i * NTHREADS;
        int n = idx >> 3, seg = idx & 7;
        uint32_t dst = wsmem + n * (WW * 4) + seg * 16;
        const char* src = (const char*)(gb + (size_t)n * rowstride) + seg * 16;
        CP_ASYNC16(dst, src);
    }
    CP_COMMIT();
}

// ---------------- fp16 gemm: 64-K chunk, warp tile 32x64 ----------------
__device__ __forceinline__ void gemm_chunk(float acc[2][8][4],
                                           const uint32_t* __restrict__ hw,
                                           const uint32_t* __restrict__ ww,
                                           int kwbase, int wm, int wn, int lg, int tig) {
#pragma unroll
    for (int ks = 0; ks < 4; ++ks) {
        uint32_t a[2][4];
#pragma unroll
        for (int mt = 0; mt < 2; ++mt) {
            const uint32_t* ap = hw + (wm * 32 + mt * 16 + lg) * HW + kwbase + ks * 8;
            a[mt][0] = ap[tig];
            a[mt][1] = ap[8 * HW + tig];
            a[mt][2] = ap[tig + 4];
            a[mt][3] = ap[8 * HW + tig + 4];
        }
#pragma unroll
        for (int nt = 0; nt < 8; ++nt) {
            const uint32_t* bp = ww + (wn * 64 + nt * 8 + lg) * WW + ks * 8;
            uint32_t b0 = bp[tig];
            uint32_t b1 = bp[tig + 4];
            mma16(acc[0][nt], a[0], b0, b1);
            mma16(acc[1][nt], a[1], b0, b1);
        }
    }
}

// ---------------- main ----------------
__global__ __launch_bounds__(NTHREADS, 1)
void fno_main(const float* __restrict__ mu, const float* __restrict__ xin,
              const float* __restrict__ b1, const float* __restrict__ W2,
              const float* __restrict__ b2v, float* __restrict__ out) {
    extern __shared__ __align__(16) char smem[];
    const uint32_t sb = smem_u32(smem);
    uint32_t* hw = (uint32_t*)smem;
    float* g_all = (float*)(smem + G_OFF);
    float* x_s   = (float*)(smem + X_OFF);
    float* w2_s  = (float*)(smem + W2_OFF);

    const int tid  = threadIdx.x;
    const int lane = tid & 31;
    const int warp = tid >> 5;
    const int lg   = lane >> 2;
    const int tig  = lane & 3;
    const int wm   = warp >> 2;
    const int wn   = warp & 3;
    const size_t row0 = (size_t)blockIdx.x * MROWS;

    // start streaming encoder weights immediately
    prefetch_chunk(0, sb + WBUF0_OFF, tid);

    // g_all: [0]=b1, [1..4]=g layers
    for (int i = tid; i < 5 * NMODES; i += NTHREADS)
        g_all[i] = (i < NMODES) ? b1[i] : g_dev[i - NMODES];
    for (int i = tid; i < MROWS * 3; i += NTHREADS) {
        int r = i / 3, c = i - r * 3;
        x_s[r * 4 + c] = xin[(row0 + r) * 3 + c];
    }
    if (tid < NMODES) w2_s[tid] = W2[tid];

    // mu -> h fp16 words [r][0..31]
    for (int i = tid; i < MROWS * 32; i += NTHREADS) {
        int r = i >> 5, w = i & 31;
        float2 v = ((const float2*)(mu + (row0 + r) * 64))[w];
        __half2 h2 = __floats2half2_rn(v.x, v.y);
        hw[r * HW + w] = *(const uint32_t*)&h2;
    }

    float acc[2][8][4];
    int id = 0;
    for (int stage = 0; stage < 5; ++stage) {
        const int nch = (stage == 0) ? 1 : 4;
#pragma unroll
        for (int mt = 0; mt < 2; ++mt)
#pragma unroll
            for (int nt = 0; nt < 8; ++nt)
#pragma unroll
                for (int j = 0; j < 4; ++j) acc[mt][nt][j] = 0.0f;

#pragma unroll 1
        for (int c = 0; c < nch; ++c) {
            __syncthreads();   // buffer (id+1)&1 free; h writes visible
            if (id + 1 < 17) {
                prefetch_chunk(id + 1, sb + ((id + 1) & 1 ? WBUF1_OFF : WBUF0_OFF), tid);
                CP_WAIT(1);    // chunk id has landed
            } else {
                CP_WAIT(0);
            }
            __syncthreads();
            const uint32_t* ww = (const uint32_t*)(smem + ((id & 1) ? WBUF1_OFF : WBUF0_OFF));
            gemm_chunk(acc, hw, ww, (stage == 0) ? 0 : c * 32, wm, wn, lg, tig);
            ++id;
        }
        __syncthreads();   // all warps done reading h for this stage

        // epilogue
        const float* gs = g_all + stage * NMODES;
        const bool last = (stage == 4);
#pragma unroll
        for (int mt = 0; mt < 2; ++mt)
#pragma unroll
            for (int half = 0; half < 2; ++half) {
                int r = wm * 32 + mt * 16 + half * 8 + lg;
                float x0 = x_s[r * 4 + 0];
                float x1 = x_s[r * 4 + 1];
                float x2 = x_s[r * 4 + 2];
#pragma unroll
                for (int nt = 0; nt < 8; ++nt) {
                    int n = wn * 64 + nt * 8 + 2 * tig;
                    float v0 = acc[mt][nt][half * 2 + 0];
                    float v1 = acc[mt][nt][half * 2 + 1];
                    if (stage == 0) {
                        v0 += gs[n]; v1 += gs[n + 1];
                    } else {
                        v0 += x0 * gs[n] + x1 * gs[(n + 255) & 255] + x2 * gs[(n + 254) & 255];
                        int n1 = n + 1;
                        v1 += x0 * gs[n1] + x1 * gs[(n1 + 255) & 255] + x2 * gs[(n1 + 254) & 255];
                    }
                    v0 = fmaxf(v0, 0.0f);
                    v1 = fmaxf(v1, 0.0f);
                    if (!last) {
                        __half2 h2 = __floats2half2_rn(v0, v1);
                        hw[r * HW + wn * 32 + nt * 4 + tig] = *(const uint32_t*)&h2;
                    } else {
                        // final h in fp32 (overlaps dead fp16 h + weight bufs)
                        *(float2*)((float*)smem + r * FH_STRIDE + n) = make_float2(v0, v1);
                    }
                }
            }
    }
    __syncthreads();

    // decoder: out[r] = h[r,:] . W2 + b2   (4 lanes per row)
    {
        const int r = tid >> 2, p = tid & 3;
        const float* hp = (const float*)smem + r * FH_STRIDE + p * 64;
        const float* wp = w2_s + p * 64;
        float s = 0.0f;
#pragma unroll
        for (int i = 0; i < 64; i += 2) {
            int j = (i + 8 * p) & 63;   // bank-rotate across parts
            float2 hv = *(const float2*)(hp + j);
            s += hv.x * wp[j] + hv.y * wp[j + 1];
        }
        s += __shfl_xor_sync(0xffffffffu, s, 1);
        s += __shfl_xor_sync(0xffffffffu, s, 2);
        if (p == 0) out[row0 + r] = s + b2v[0];
    }
}

// ---------------------------------------------------------------------------
extern "C" void kernel_launch(void* const* d_in, const int* in_sizes, int n_in,
                              void* d_out, int out_size) {
    const float* mu = (const float*)d_in[0];
    const float* x  = (const float*)d_in[1];
    const float* W1 = (const float*)d_in[2];
    const float* b1 = (const float*)d_in[3];
    const float* fw = (const float*)d_in[4];
    const float* lw = (const float*)d_in[5];
    const float* W2 = (const float*)d_in[6];
    const float* b2 = (const float*)d_in[7];
    float* out = (float*)d_out;

    const int B = in_sizes[0] / 64;
    const int nblocks = B / MROWS;

    build_g<<<NLAYERS, NMODES>>>(fw);
    build_Bth<<<NLAYERS * NMODES, NMODES>>>(lw);
    build_w1th<<<NMODES, 64>>>(W1);

    cudaFuncSetAttribute(fno_main, cudaFuncAttributeMaxDynamicSharedMemorySize, SMEM_TOTAL);
    fno_main<<<nblocks, NTHREADS, SMEM_TOTAL>>>(mu, x, b1, W2, b2, out);
}

// round 4
// speedup vs baseline: 1.9508x; 1.1135x over previous
#include <cuda_runtime.h>
#include <cuda_fp16.h>
#include <cstdint>

// ---------------------------------------------------------------------------
// FNO on sm_103a, fp16 HMMA (m16n8k16) + ldmatrix + cp.async double buffer.
//   h0 = relu(mu @ W1 + b1)
//   h  = relu(h @ B_l + x-term_l)   l=0..3  (circulant form of rfft*fw->irfft)
//   out = h @ W2 + b2
// 256 threads/CTA, 64 rows/CTA, 112KB SMEM -> 2 CTAs/SM for overlap.
// ---------------------------------------------------------------------------

#define NMODES 256
#define NLAYERS 4
#define MROWS 64
#define NTHREADS 256
#define HW 132                       // h row stride in 32-bit words
#define WW 36                        // weight row stride in words
#define H_BYTES (MROWS * HW * 4)     // 33792
#define WBUF0_OFF H_BYTES
#define WBUF_BYTES (NMODES * WW * 4) // 36864
#define WBUF1_OFF (WBUF0_OFF + WBUF_BYTES)
#define G_OFF  (WBUF1_OFF + WBUF_BYTES)      // 107520
#define X_OFF  (G_OFF + 5 * NMODES * 4)      // 112640
#define W2_OFF (X_OFF + MROWS * 4 * 4)       // 113664
#define SMEM_TOTAL (W2_OFF + NMODES * 4)     // 114688 = 112KB
#define FH_STRIDE 260                // final fp32 h row stride (floats)

__device__ float  g_dev[NLAYERS * NMODES];
__device__ __align__(16) __half Bt_h[NLAYERS * NMODES * NMODES]; // [l][n][k]
__device__ __align__(16) __half w1t_h[NMODES * 64];              // [n][k]

__device__ __forceinline__ uint32_t smem_u32(const void* p) {
    uint32_t a;
    asm("{ .reg .u64 t; cvta.to.shared.u64 t, %1; cvt.u32.u64 %0, t; }" : "=r"(a) : "l"(p));
    return a;
}

#define CP_ASYNC16(dst, src) \
    asm volatile("cp.async.cg.shared.global [%0], [%1], 16;" :: "r"(dst), "l"(src) : "memory")
#define CP_COMMIT() asm volatile("cp.async.commit_group;" ::: "memory")
#define CP_WAIT(n)  asm volatile("cp.async.wait_group %0;" :: "n"(n) : "memory")

__device__ __forceinline__ void mma16(float* c, const uint32_t* a, uint32_t b0, uint32_t b1) {
    asm volatile(
        "mma.sync.aligned.m16n8k16.row.col.f32.f16.f16.f32 "
        "{%0,%1,%2,%3}, {%4,%5,%6,%7}, {%8,%9}, {%0,%1,%2,%3};\n"
        : "+f"(c[0]), "+f"(c[1]), "+f"(c[2]), "+f"(c[3])
        : "r"(a[0]), "r"(a[1]), "r"(a[2]), "r"(a[3]), "r"(b0), "r"(b1));
}

__device__ __forceinline__ void ldsm_x4(uint32_t& r0, uint32_t& r1, uint32_t& r2, uint32_t& r3,
                                        uint32_t addr) {
    asm volatile("ldmatrix.sync.aligned.m8n8.x4.shared.b16 {%0,%1,%2,%3}, [%4];"
                 : "=r"(r0), "=r"(r1), "=r"(r2), "=r"(r3) : "r"(addr));
}

// ---------------- preludes ----------------
__global__ void build_g(const float* __restrict__ fw) {
    int l = blockIdx.x, n = threadIdx.x;
    const float* f = fw + l * 129;
    float acc = f[0] + ((n & 1) ? -f[128] : f[128]);
    float nn = (float)n;
#pragma unroll 4
    for (int k = 1; k < 128; ++k)
        acc += 2.0f * f[k] * cospif((float)k * nn * (1.0f / 128.0f));
    g_dev[l * NMODES + n] = acc * (1.0f / 256.0f);
}

__global__ void build_Bth(const float* __restrict__ lw) {
    int l = blockIdx.x >> 8, n = blockIdx.x & 255, k = threadIdx.x;
    float v = (k <= 252) ? g_dev[l * NMODES + ((n - k - 3) & 255)] : 0.0f;
    if (k == n) v += lw[l * NMODES + k];
    Bt_h[((size_t)(l * NMODES + n)) * NMODES + k] = __float2half_rn(v);
}

__global__ void build_w1th(const float* __restrict__ W1) {
    int n = blockIdx.x, k = threadIdx.x;
    w1t_h[n * 64 + k] = __float2half_rn(W1[k * NMODES + n]);
}

// ---------------- weight-chunk prefetch ----------------
// id 0: encoder (w1t_h); id 1..16: layer (id-1)>>2, k0 = ((id-1)&3)*64
__device__ __forceinline__ void prefetch_chunk(int id, uint32_t wsmem, int tid) {
    const __half* gb;
    int rowstride;
    if (id == 0) { gb = w1t_h; rowstride = 64; }
    else {
        int t = id - 1;
        gb = Bt_h + (((size_t)((t >> 2) * NMODES)) << 8) + (t & 3) * 64;
        rowstride = NMODES;
    }
#pragma unroll
    for (int i = 0; i < 8; ++i) {
        int idx = tid + i * NTHREADS;
        int n = idx >> 3, seg = idx & 7;
        uint32_t dst = wsmem + n * (WW * 4) + seg * 16;
        const char* src = (const char*)(gb + (size_t)n * rowstride) + seg * 16;
        CP_ASYNC16(dst, src);
    }
    CP_COMMIT();
}

// ---------------- main ----------------
__global__ __launch_bounds__(NTHREADS, 2)
void fno_main(const float* __restrict__ mu, const float* __restrict__ xin,
              const float* __restrict__ b1, const float* __restrict__ W2,
              const float* __restrict__ b2v, float* __restrict__ out) {
    extern __shared__ __align__(16) char smem[];
    const uint32_t sb = smem_u32(smem);
    uint32_t* hw = (uint32_t*)smem;
    float* g_all = (float*)(smem + G_OFF);
    float* x_s   = (float*)(smem + X_OFF);
    float* w2_s  = (float*)(smem + W2_OFF);

    const int tid  = threadIdx.x;
    const int lane = tid & 31;
    const int warp = tid >> 5;
    const int lg   = lane >> 2;
    const int tig  = lane & 3;
    const int wm   = warp >> 2;   // 0..1
    const int wn   = warp & 3;    // 0..3
    const size_t row0 = (size_t)blockIdx.x * MROWS;

    prefetch_chunk(0, sb + WBUF0_OFF, tid);

    for (int i = tid; i < 5 * NMODES; i += NTHREADS)
        g_all[i] = (i < NMODES) ? b1[i] : g_dev[i - NMODES];
    for (int i = tid; i < MROWS * 3; i += NTHREADS) {
        int r = i / 3, c = i - r * 3;
        x_s[r * 4 + c] = xin[(row0 + r) * 3 + c];
    }
    if (tid < NMODES) w2_s[tid] = W2[tid];

    // mu -> h fp16 words [r][0..31]
    for (int i = tid; i < MROWS * 32; i += NTHREADS) {
        int r = i >> 5, w = i & 31;
        float2 v = ((const float2*)(mu + (row0 + r) * 64))[w];
        __half2 h2 = __floats2half2_rn(v.x, v.y);
        hw[r * HW + w] = *(const uint32_t*)&h2;
    }

    // ldmatrix per-lane address bases
    // A: tiles (rows0-7,k0-15B)(rows8-15,k0-15B)(rows0-7,k16-31B)(rows8-15,k16-31B)
    const int a_row = lane & 15;
    const uint32_t a_koff = (uint32_t)((lane >> 4) << 4);
    uint32_t a_base[2];
#pragma unroll
    for (int mt = 0; mt < 2; ++mt)
        a_base[mt] = sb + (wm * 32 + mt * 16 + a_row) * (HW * 4) + a_koff;
    // B: tiles (n0-7,k0-15B)(n0-7,k16-31B)(n8-15,k0-15B)(n8-15,k16-31B)
    const int b_nloc = ((lane & 16) >> 1) + (lane & 7);
    const uint32_t b_koff = (uint32_t)((lane & 8) << 1);
    uint32_t b_off[4];
#pragma unroll
    for (int ntp = 0; ntp < 4; ++ntp)
        b_off[ntp] = (wn * 64 + ntp * 16 + b_nloc) * (WW * 4) + b_koff;

    float acc[2][8][4];
    int id = 0;
    for (int stage = 0; stage < 5; ++stage) {
        const int nch = (stage == 0) ? 1 : 4;
#pragma unroll
        for (int mt = 0; mt < 2; ++mt)
#pragma unroll
            for (int nt = 0; nt < 8; ++nt)
#pragma unroll
                for (int j = 0; j < 4; ++j) acc[mt][nt][j] = 0.0f;

#pragma unroll 1
        for (int c = 0; c < nch; ++c) {
            __syncthreads();   // other buffer free; h writes visible
            if (id + 1 < 17) {
                prefetch_chunk(id + 1, sb + ((id + 1) & 1 ? WBUF1_OFF : WBUF0_OFF), tid);
                CP_WAIT(1);
            } else {
                CP_WAIT(0);
            }
            __syncthreads();
            const uint32_t wbase = sb + ((id & 1) ? WBUF1_OFF : WBUF0_OFF);
            const int kwbase = (stage == 0) ? 0 : c * 32;
#pragma unroll
            for (int ks = 0; ks < 4; ++ks) {
                uint32_t a[2][4];
#pragma unroll
                for (int mt = 0; mt < 2; ++mt)
                    ldsm_x4(a[mt][0], a[mt][1], a[mt][2], a[mt][3],
                            a_base[mt] + (kwbase + ks * 8) * 4);
#pragma unroll
                for (int ntp = 0; ntp < 4; ++ntp) {
                    uint32_t b0, b1, b2, b3;
                    ldsm_x4(b0, b1, b2, b3, wbase + b_off[ntp] + ks * 32);
                    mma16(acc[0][2 * ntp],     a[0], b0, b1);
                    mma16(acc[1][2 * ntp],     a[1], b0, b1);
                    mma16(acc[0][2 * ntp + 1], a[0], b2, b3);
                    mma16(acc[1][2 * ntp + 1], a[1], b2, b3);
                }
            }
            ++id;
        }
        __syncthreads();   // all warps done reading h

        // epilogue
        const float* gs = g_all + stage * NMODES;
        const bool last = (stage == 4);
#pragma unroll
        for (int mt = 0; mt < 2; ++mt)
#pragma unroll
            for (int half = 0; half < 2; ++half) {
                int r = wm * 32 + mt * 16 + half * 8 + lg;
                float x0 = x_s[r * 4 + 0];
                float x1 = x_s[r * 4 + 1];
                float x2 = x_s[r * 4 + 2];
#pragma unroll
                for (int nt = 0; nt < 8; ++nt) {
                    int n = wn * 64 + nt * 8 + 2 * tig;
                    float v0 = acc[mt][nt][half * 2 + 0];
                    float v1 = acc[mt][nt][half * 2 + 1];
                    if (stage == 0) {
                        v0 += gs[n]; v1 += gs[n + 1];
                    } else {
                        v0 += x0 * gs[n] + x1 * gs[(n + 255) & 255] + x2 * gs[(n + 254) & 255];
                        int n1 = n + 1;
                        v1 += x0 * gs[n1] + x1 * gs[(n1 + 255) & 255] + x2 * gs[(n1 + 254) & 255];
                    }
                    v0 = fmaxf(v0, 0.0f);
                    v1 = fmaxf(v1, 0.0f);
                    if (!last) {
                        __half2 h2 = __floats2half2_rn(v0, v1);
                        hw[r * HW + wn * 32 + nt * 4 + tig] = *(const uint32_t*)&h2;
                    } else {
                        *(float2*)((float*)smem + r * FH_STRIDE + n) = make_float2(v0, v1);
                    }
                }
            }
    }
    __syncthreads();

    // decoder: out[r] = h[r,:] . W2 + b2   (4 lanes per row)
    {
        const int r = tid >> 2, p = tid & 3;
        const float* hp = (const float*)smem + r * FH_STRIDE + p * 64;
        const float* wp = w2_s + p * 64;
        float s = 0.0f;
#pragma unroll
        for (int i = 0; i < 64; i += 2) {
            int j = (i + 8 * p) & 63;
            float2 hv = *(const float2*)(hp + j);
            s += hv.x * wp[j] + hv.y * wp[j + 1];
        }
        s += __shfl_xor_sync(0xffffffffu, s, 1);
        s += __shfl_xor_sync(0xffffffffu, s, 2);
        if (p == 0) out[row0 + r] = s + b2v[0];
    }
}

// ---------------------------------------------------------------------------
extern "C" void kernel_launch(void* const* d_in, const int* in_sizes, int n_in,
                              void* d_out, int out_size) {
    const float* mu = (const float*)d_in[0];
    const float* x  = (const float*)d_in[1];
    const float* W1 = (const float*)d_in[2];
    const float* b1 = (const float*)d_in[3];
    const float* fw = (const float*)d_in[4];
    const float* lw = (const float*)d_in[5];
    const float* W2 = (const float*)d_in[6];
    const float* b2 = (const float*)d_in[7];
    float* out = (float*)d_out;

    const int B = in_sizes[0] / 64;
    const int nblocks = B / MROWS;

    build_g<<<NLAYERS, NMODES>>>(fw);
    build_Bth<<<NLAYERS * NMODES, NMODES>>>(lw);
    build_w1th<<<NMODES, 64>>>(W1);

    cudaFuncSetAttribute(fno_main, cudaFuncAttributeMaxDynamicSharedMemorySize, SMEM_TOTAL);
    fno_main<<<nblocks, NTHREADS, SMEM_TOTAL>>>(mu, x, b1, W2, b2, out);
}

// round 5
// speedup vs baseline: 2.3985x; 1.2295x over previous
#include <cuda_runtime.h>
#include <cuda_fp16.h>
#include <cstdint>

// ---------------------------------------------------------------------------
// FNO on sm_103a, fp16 HMMA (m16n8k16) + swizzled-weight cp.async pipeline.
//   h0 = relu(mu @ W1 + b1)
//   h  = relu(h @ B_l + x-term_l)   l=0..3  (circulant form of rfft*fw->irfft)
//   out = h @ W2 + b2
// Weights pre-packed in global EXACTLY as the smem image (XOR-swizzled 128B
// rows, 32KB per 64-K chunk) -> linear cp.async, conflict-free ldmatrix.
// 256 threads, 64 rows/CTA, 104KB SMEM -> 2 CTAs/SM. B fragments double-
// buffered; A reloaded once per ks after last use.
// ---------------------------------------------------------------------------

#define NMODES 256
#define NLAYERS 4
#define MROWS 64
#define NTHREADS 256
#define HW 132                        // h row stride in 32-bit words
#define H_BYTES (MROWS * HW * 4)      // 33792
#define WBUF_BYTES (NMODES * 128)     // 32768 (swizzled, no pad)
#define WBUF0_OFF H_BYTES
#define WBUF1_OFF (WBUF0_OFF + WBUF_BYTES)
#define G_OFF  (WBUF1_OFF + WBUF_BYTES)      // 99328
#define X_OFF  (G_OFF + 5 * NMODES * 4)      // 104448
#define W2_OFF (X_OFF + MROWS * 4 * 4)       // 105472
#define SMEM_TOTAL (W2_OFF + NMODES * 4)     // 106496 = 104KB
#define FH_STRIDE 260                 // final fp32 h row stride (floats)
#define NCHUNKS (1 + NLAYERS * 4)     // 17

__device__ float g_dev[NLAYERS * NMODES];
// packed weight image: [chunk][n][64 halves], row pre-swizzled so that the
// 16B segment at position p holds source k-segment (p ^ (n&7)).
__device__ __align__(16) __half w_sw[NCHUNKS * NMODES * 64];

__device__ __forceinline__ uint32_t smem_u32(const void* p) {
    uint32_t a;
    asm("{ .reg .u64 t; cvta.to.shared.u64 t, %1; cvt.u32.u64 %0, t; }" : "=r"(a) : "l"(p));
    return a;
}

#define CP_ASYNC16(dst, src) \
    asm volatile("cp.async.cg.shared.global [%0], [%1], 16;" :: "r"(dst), "l"(src) : "memory")
#define CP_COMMIT() asm volatile("cp.async.commit_group;" ::: "memory")
#define CP_WAIT(n)  asm volatile("cp.async.wait_group %0;" :: "n"(n) : "memory")

__device__ __forceinline__ void mma16(float* c, const uint32_t* a, uint32_t b0, uint32_t b1) {
    asm volatile(
        "mma.sync.aligned.m16n8k16.row.col.f32.f16.f16.f32 "
        "{%0,%1,%2,%3}, {%4,%5,%6,%7}, {%8,%9}, {%0,%1,%2,%3};\n"
        : "+f"(c[0]), "+f"(c[1]), "+f"(c[2]), "+f"(c[3])
        : "r"(a[0]), "r"(a[1]), "r"(a[2]), "r"(a[3]), "r"(b0), "r"(b1));
}

__device__ __forceinline__ void ldsm_x4(uint32_t& r0, uint32_t& r1, uint32_t& r2, uint32_t& r3,
                                        uint32_t addr) {
    asm volatile("ldmatrix.sync.aligned.m8n8.x4.shared.b16 {%0,%1,%2,%3}, [%4];"
                 : "=r"(r0), "=r"(r1), "=r"(r2), "=r"(r3) : "r"(addr));
}

// ---------------- preludes ----------------
__global__ void build_g(const float* __restrict__ fw) {
    int l = blockIdx.x, n = threadIdx.x;
    const float* f = fw + l * 129;
    float acc = f[0] + ((n & 1) ? -f[128] : f[128]);
    float nn = (float)n;
#pragma unroll 4
    for (int k = 1; k < 128; ++k)
        acc += 2.0f * f[k] * cospif((float)k * nn * (1.0f / 128.0f));
    g_dev[l * NMODES + n] = acc * (1.0f / 256.0f);
}

// chunk 0: encoder W1^T; chunks 1..16: circulant B_l^T (64-K slices), all
// pre-swizzled: element stored at (n, pos*8+jj) comes from source
// k = (pos ^ (n&7))*8 + jj within the chunk.
__global__ void build_wsw(const float* __restrict__ W1, const float* __restrict__ lw) {
    int id = blockIdx.x >> 8;
    int n  = blockIdx.x & 255;
    int j  = threadIdx.x;           // 0..63
    int pos = j >> 3, jj = j & 7;
    int k = ((pos ^ (n & 7)) << 3) + jj;
    float v;
    if (id == 0) {
        v = W1[k * NMODES + n];
    } else {
        int t = id - 1, l = t >> 2;
        int kg = (t & 3) * 64 + k;
        v = (kg <= 252) ? g_dev[l * NMODES + ((n - kg - 3) & 255)] : 0.0f;
        if (kg == n) v += lw[l * NMODES + kg];
    }
    w_sw[(((size_t)id << 8) + n) * 64 + j] = __float2half_rn(v);
}

// ---------------- weight-chunk prefetch (linear copy of packed image) -------
__device__ __forceinline__ void prefetch_chunk(int id, uint32_t wsmem, int tid) {
    const char* src = (const char*)(w_sw + ((size_t)id << 14));
#pragma unroll
    for (int i = 0; i < 8; ++i) {
        int idx = tid + i * NTHREADS;
        CP_ASYNC16(wsmem + idx * 16, src + idx * 16);
    }
    CP_COMMIT();
}

// ---------------- main ----------------
__global__ __launch_bounds__(NTHREADS, 2)
void fno_main(const float* __restrict__ mu, const float* __restrict__ xin,
              const float* __restrict__ b1, const float* __restrict__ W2,
              const float* __restrict__ b2v, float* __restrict__ out) {
    extern __shared__ __align__(16) char smem[];
    const uint32_t sb = smem_u32(smem);
    uint32_t* hw = (uint32_t*)smem;
    float* g_all = (float*)(smem + G_OFF);
    float* x_s   = (float*)(smem + X_OFF);
    float* w2_s  = (float*)(smem + W2_OFF);

    const int tid  = threadIdx.x;
    const int lane = tid & 31;
    const int warp = tid >> 5;
    const int lg   = lane >> 2;
    const int tig  = lane & 3;
    const int wm   = warp >> 2;   // 0..1
    const int wn   = warp & 3;    // 0..3
    const size_t row0 = (size_t)blockIdx.x * MROWS;

    prefetch_chunk(0, sb + WBUF0_OFF, tid);

    for (int i = tid; i < 5 * NMODES; i += NTHREADS)
        g_all[i] = (i < NMODES) ? b1[i] : g_dev[i - NMODES];
    for (int i = tid; i < MROWS * 3; i += NTHREADS) {
        int r = i / 3, c = i - r * 3;
        x_s[r * 4 + c] = xin[(row0 + r) * 3 + c];
    }
    if (tid < NMODES) w2_s[tid] = W2[tid];

    // mu -> h fp16 words [r][0..31]
    for (int i = tid; i < MROWS * 32; i += NTHREADS) {
        int r = i >> 5, w = i & 31;
        float2 v = ((const float2*)(mu + (row0 + r) * 64))[w];
        __half2 h2 = __floats2half2_rn(v.x, v.y);
        hw[r * HW + w] = *(const uint32_t*)&h2;
    }

    // ldmatrix lane bases
    // A: tiles (m0-7,k0-7h)(m8-15,k0-7h)(m0-7,k8-15h)(m8-15,k8-15h)
    const int a_row = lane & 15;
    const uint32_t a_koff = (uint32_t)((lane >> 4) << 4);
    uint32_t a_base[2];
#pragma unroll
    for (int mt = 0; mt < 2; ++mt)
        a_base[mt] = sb + (wm * 32 + mt * 16 + a_row) * (HW * 4) + a_koff;
    // B (swizzled rows): n-row per lane; seg index per ks with lane-half bit
    const int b_nloc = ((lane & 16) >> 1) + (lane & 7);
    const int hi = (lane >> 3) & 1;
    uint32_t b_base[4];
    int bx[4];
#pragma unroll
    for (int ntp = 0; ntp < 4; ++ntp) {
        int n = wn * 64 + ntp * 16 + b_nloc;
        b_base[ntp] = (uint32_t)(n << 7);
        bx[ntp] = n & 7;
    }

    float acc[2][8][4];
    int id = 0;
    for (int stage = 0; stage < 5; ++stage) {
        const int nch = (stage == 0) ? 1 : 4;
#pragma unroll
        for (int mt = 0; mt < 2; ++mt)
#pragma unroll
            for (int nt = 0; nt < 8; ++nt)
#pragma unroll
                for (int j = 0; j < 4; ++j) acc[mt][nt][j] = 0.0f;

#pragma unroll 1
        for (int c = 0; c < nch; ++c) {
            __syncthreads();   // other buffer free; h writes visible
            if (id + 1 < NCHUNKS) {
                prefetch_chunk(id + 1, sb + ((id + 1) & 1 ? WBUF1_OFF : WBUF0_OFF), tid);
                CP_WAIT(1);
            } else {
                CP_WAIT(0);
            }
            __syncthreads();
            const uint32_t wbase = sb + ((id & 1) ? WBUF1_OFF : WBUF0_OFF);
            const int kwbase = (stage == 0) ? 0 : c * 32;   // words

            uint32_t a[2][4], bb[2][4];
            ldsm_x4(a[0][0], a[0][1], a[0][2], a[0][3], a_base[0] + kwbase * 4);
            ldsm_x4(a[1][0], a[1][1], a[1][2], a[1][3], a_base[1] + kwbase * 4);
            ldsm_x4(bb[0][0], bb[0][1], bb[0][2], bb[0][3],
                    wbase + b_base[0] + (uint32_t)(((0 ^ hi ^ bx[0]) & 7) << 4)
                          + (uint32_t)(hi ? 0 : 0));
            // note: seg = ks*2 + hi; above is ks=0,ntp=0
#pragma unroll
            for (int i = 0; i < 16; ++i) {
                const int ks = i >> 2, ntp = i & 3;
                uint32_t* bc = bb[i & 1];
                uint32_t* bn = bb[(i + 1) & 1];
                if (i < 15) {
                    const int i2 = i + 1, ks2 = i2 >> 2, ntp2 = i2 & 3;
                    const int seg2 = ks2 * 2 + hi;
                    ldsm_x4(bn[0], bn[1], bn[2], bn[3],
                            wbase + b_base[ntp2] + (uint32_t)(((seg2 ^ bx[ntp2]) & 7) << 4));
                }
                mma16(acc[0][2 * ntp],     a[0], bc[0], bc[1]);
                mma16(acc[1][2 * ntp],     a[1], bc[0], bc[1]);
                mma16(acc[0][2 * ntp + 1], a[0], bc[2], bc[3]);
                mma16(acc[1][2 * ntp + 1], a[1], bc[2], bc[3]);
                if (ntp == 3 && ks < 3) {
                    const int kw = kwbase + (ks + 1) * 8;
                    ldsm_x4(a[0][0], a[0][1], a[0][2], a[0][3], a_base[0] + kw * 4);
                    ldsm_x4(a[1][0], a[1][1], a[1][2], a[1][3], a_base[1] + kw * 4);
                }
            }
            ++id;
        }
        __syncthreads();   // all warps done reading h

        // epilogue
        const float* gs = g_all + stage * NMODES;
        const bool last = (stage == 4);
#pragma unroll
        for (int mt = 0; mt < 2; ++mt)
#pragma unroll
            for (int half = 0; half < 2; ++half) {
                int r = wm * 32 + mt * 16 + half * 8 + lg;
                float x0 = x_s[r * 4 + 0];
                float x1 = x_s[r * 4 + 1];
                float x2 = x_s[r * 4 + 2];
#pragma unroll
                for (int nt = 0; nt < 8; ++nt) {
                    int n = wn * 64 + nt * 8 + 2 * tig;
                    float v0 = acc[mt][nt][half * 2 + 0];
                    float v1 = acc[mt][nt][half * 2 + 1];
                    if (stage == 0) {
                        v0 += gs[n]; v1 += gs[n + 1];
                    } else {
                        v0 += x0 * gs[n] + x1 * gs[(n + 255) & 255] + x2 * gs[(n + 254) & 255];
                        int n1 = n + 1;
                        v1 += x0 * gs[n1] + x1 * gs[(n1 + 255) & 255] + x2 * gs[(n1 + 254) & 255];
                    }
                    v0 = fmaxf(v0, 0.0f);
                    v1 = fmaxf(v1, 0.0f);
                    if (!last) {
                        __half2 h2 = __floats2half2_rn(v0, v1);
                        hw[r * HW + wn * 32 + nt * 4 + tig] = *(const uint32_t*)&h2;
                    } else {
                        *(float2*)((float*)smem + r * FH_STRIDE + n) = make_float2(v0, v1);
                    }
                }
            }
    }
    __syncthreads();

    // decoder: out[r] = h[r,:] . W2 + b2   (4 lanes per row)
    {
        const int r = tid >> 2, p = tid & 3;
        const float* hp = (const float*)smem + r * FH_STRIDE + p * 64;
        const float* wp = w2_s + p * 64;
        float s = 0.0f;
#pragma unroll
        for (int i = 0; i < 64; i += 2) {
            int j = (i + 8 * p) & 63;
            float2 hv = *(const float2*)(hp + j);
            s += hv.x * wp[j] + hv.y * wp[j + 1];
        }
        s += __shfl_xor_sync(0xffffffffu, s, 1);
        s += __shfl_xor_sync(0xffffffffu, s, 2);
        if (p == 0) out[row0 + r] = s + b2v[0];
    }
}

// ---------------------------------------------------------------------------
extern "C" void kernel_launch(void* const* d_in, const int* in_sizes, int n_in,
                              void* d_out, int out_size) {
    const float* mu = (const float*)d_in[0];
    const float* x  = (const float*)d_in[1];
    const float* W1 = (const float*)d_in[2];
    const float* b1 = (const float*)d_in[3];
    const float* fw = (const float*)d_in[4];
    const float* lw = (const float*)d_in[5];
    const float* W2 = (const float*)d_in[6];
    const float* b2 = (const float*)d_in[7];
    float* out = (float*)d_out;

    const int B = in_sizes[0] / 64;
    const int nblocks = B / MROWS;

    build_g<<<NLAYERS, NMODES>>>(fw);
    build_wsw<<<NCHUNKS * NMODES, 64>>>(W1, lw);

    cudaFuncSetAttribute(fno_main, cudaFuncAttributeMaxDynamicSharedMemorySize, SMEM_TOTAL);
    fno_main<<<nblocks, NTHREADS, SMEM_TOTAL>>>(mu, x, b1, W2, b2, out);
}